// round 15
// baseline (speedup 1.0000x reference)
#include <cuda_runtime.h>
#include <cuda_bf16.h>
#include <cstdint>

#define SIZE   4096
#define NDOWN  256
#define NT     16
#define MAXB   4096
#define MTILE  128
#define KSPLIT 4
#define KCHUNK (SIZE / KSPLIT)   // 1024
#define KTILE  32

#define AST 40    // A smem stride (bf16)
#define BST 136   // B smem stride (down, 128-wide)
#define BST2 72   // B smem stride (up, 64-wide)

// ---- down kernel smem layout ----
#define A_STAGE    (MTILE * AST * 2)             // 10240
#define BF32_OFF   (3 * A_STAGE)                 // 30720
#define BF32_STAGE (KTILE * 128 * 4)             // 16384
#define BB16_OFF   (BF32_OFF + 3 * BF32_STAGE)   // 79872
#define BB16_STAGE (KTILE * BST * 2)             // 8704
#define D_SMEM     (BB16_OFF + 3 * BB16_STAGE)   // 105984

// ---- up kernel smem layout: 4-stage A ring + 2-slot bf16 B ring ----
#define U_ASTAGES  4
#define U_B_OFF    (U_ASTAGES * A_STAGE)         // 40960
#define UB16_STAGE (KTILE * BST2 * 2)            // 4608
#define U_SMEM     (U_B_OFF + 2 * UB16_STAGE)    // 50176 -> 3 CTAs/SM

// ---------------- device scratch ----------------
__device__ int   g_offsets[NT + 1];
__device__ int   g_sorted[MAXB];
__device__ int   g_rowtask[MAXB];
__device__ int   g_work_t[MAXB / MTILE + NT];
__device__ int   g_work_m0[MAXB / MTILE + NT];
__device__ int   g_nwork;
__device__ __align__(16) __nv_bfloat16 g_part[KSPLIT][MAXB][NDOWN];
__device__ __align__(16) __nv_bfloat16 g_act[(size_t)MAXB * NDOWN];

// ---------------- helpers ----------------
__device__ __forceinline__ uint32_t smem_u32(const void* p) {
    return (uint32_t)__cvta_generic_to_shared(p);
}
__device__ __forceinline__ void cp_async16(uint32_t dst, const void* src) {
    asm volatile("cp.async.cg.shared.global [%0], [%1], 16;\n"
                 :: "r"(dst), "l"(src) : "memory");
}
__device__ __forceinline__ void cp_commit() {
    asm volatile("cp.async.commit_group;\n" ::: "memory");
}
__device__ __forceinline__ void cp_wait1() {
    asm volatile("cp.async.wait_group 1;\n" ::: "memory");
}
__device__ __forceinline__ void cp_wait2() {
    asm volatile("cp.async.wait_group 2;\n" ::: "memory");
}
__device__ __forceinline__ uint32_t pack_bf16(float lo, float hi) {
    uint32_t r;
    asm("cvt.rn.bf16x2.f32 %0, %1, %2;" : "=r"(r) : "f"(hi), "f"(lo));
    return r;
}
__device__ __forceinline__ uint4 cvt_f4x2(float4 a, float4 b) {
    uint4 u;
    u.x = pack_bf16(a.x, a.y); u.y = pack_bf16(a.z, a.w);
    u.z = pack_bf16(b.x, b.y); u.w = pack_bf16(b.z, b.w);
    return u;
}
__device__ __forceinline__ void ldsm4(uint32_t& r0, uint32_t& r1, uint32_t& r2, uint32_t& r3,
                                      uint32_t addr) {
    asm volatile("ldmatrix.sync.aligned.m8n8.x4.shared.b16 {%0,%1,%2,%3}, [%4];"
                 : "=r"(r0), "=r"(r1), "=r"(r2), "=r"(r3) : "r"(addr));
}
__device__ __forceinline__ void ldsm4t(uint32_t& r0, uint32_t& r1, uint32_t& r2, uint32_t& r3,
                                       uint32_t addr) {
    asm volatile("ldmatrix.sync.aligned.m8n8.x4.trans.shared.b16 {%0,%1,%2,%3}, [%4];"
                 : "=r"(r0), "=r"(r1), "=r"(r2), "=r"(r3) : "r"(addr));
}
__device__ __forceinline__ void mma_bf16(float& c0, float& c1, float& c2, float& c3,
                                         uint32_t a0, uint32_t a1, uint32_t a2, uint32_t a3,
                                         uint32_t b0, uint32_t b1) {
    asm volatile(
        "mma.sync.aligned.m16n8k16.row.col.f32.bf16.bf16.f32 "
        "{%0,%1,%2,%3}, {%4,%5,%6,%7}, {%8,%9}, {%0,%1,%2,%3};\n"
        : "+f"(c0), "+f"(c1), "+f"(c2), "+f"(c3)
        : "r"(a0), "r"(a1), "r"(a2), "r"(a3), "r"(b0), "r"(b1));
}

// down warp-tile: 32(M) x 64(N) x 32(K); 8 warps = 4x2 over 128x128
__device__ __forceinline__ void compute_tile(uint32_t aSlot, uint32_t bSlot,
                                             int lane, int wm, int wn,
                                             float c[2][8][4]) {
#pragma unroll
    for (int ks = 0; ks < 2; ++ks) {
        uint32_t a[2][4];
#pragma unroll
        for (int mi = 0; mi < 2; mi++) {
            uint32_t addr = aSlot + 2u * ((wm * 32 + mi * 16 + (lane & 15)) * AST
                                          + ks * 16 + (lane >> 4) * 8);
            ldsm4(a[mi][0], a[mi][1], a[mi][2], a[mi][3], addr);
        }
        uint32_t b[8][2];
#pragma unroll
        for (int nb = 0; nb < 4; nb++) {
            uint32_t addr = bSlot + 2u * ((ks * 16 + ((lane >> 3) & 1) * 8 + (lane & 7)) * BST
                                          + wn * 64 + nb * 16 + (lane >> 4) * 8);
            ldsm4t(b[2 * nb][0], b[2 * nb][1], b[2 * nb + 1][0], b[2 * nb + 1][1], addr);
        }
#pragma unroll
        for (int mi = 0; mi < 2; mi++)
#pragma unroll
            for (int ni = 0; ni < 8; ni++)
                mma_bf16(c[mi][ni][0], c[mi][ni][1], c[mi][ni][2], c[mi][ni][3],
                         a[mi][0], a[mi][1], a[mi][2], a[mi][3],
                         b[ni][0], b[ni][1]);
    }
}

// up warp-tile: 32(M) x 32(N) x 32(K); 8 warps = 4x2 over 128x64
__device__ __forceinline__ void compute_tile_n32(uint32_t aSlot, uint32_t bSlot,
                                                 int lane, int wm, int wn,
                                                 float c[2][4][4]) {
#pragma unroll
    for (int ks = 0; ks < 2; ++ks) {
        uint32_t a[2][4];
#pragma unroll
        for (int mi = 0; mi < 2; mi++) {
            uint32_t addr = aSlot + 2u * ((wm * 32 + mi * 16 + (lane & 15)) * AST
                                          + ks * 16 + (lane >> 4) * 8);
            ldsm4(a[mi][0], a[mi][1], a[mi][2], a[mi][3], addr);
        }
        uint32_t b[4][2];
#pragma unroll
        for (int nb = 0; nb < 2; nb++) {
            uint32_t addr = bSlot + 2u * ((ks * 16 + ((lane >> 3) & 1) * 8 + (lane & 7)) * BST2
                                          + wn * 32 + nb * 16 + (lane >> 4) * 8);
            ldsm4t(b[2 * nb][0], b[2 * nb][1], b[2 * nb + 1][0], b[2 * nb + 1][1], addr);
        }
#pragma unroll
        for (int mi = 0; mi < 2; mi++)
#pragma unroll
            for (int ni = 0; ni < 4; ni++)
                mma_bf16(c[mi][ni][0], c[mi][ni][1], c[mi][ni][2], c[mi][ni][3],
                         a[mi][0], a[mi][1], a[mi][2], a[mi][3],
                         b[ni][0], b[ni][1]);
    }
}

// B-stage convert for down (self-mapped, matches fill geometry)
__device__ __forceinline__ void convert_B(char* smem, int tid, int f32slot, int b16slot) {
#pragma unroll
    for (int i = 0; i < 4; i++) {
        int f = tid + i * 256;
        int kr = f >> 5, seg = (f & 31) * 4;
        float4 v = *(const float4*)(smem + BF32_OFF + (size_t)f32slot * BF32_STAGE
                                    + ((size_t)kr * 128 + seg) * 4);
        *(uint2*)(smem + BB16_OFF + (size_t)b16slot * BB16_STAGE
                  + ((size_t)kr * BST + seg) * 2) =
            make_uint2(pack_bf16(v.x, v.y), pack_bf16(v.z, v.w));
    }
}

// ---------------- phase A: counting sort + worklist ----------------
__global__ void prep_kernel(const int* __restrict__ task_id, int B) {
    __shared__ int cnt[NT];
    __shared__ int off[NT + 1];
    __shared__ int cur[NT];
    int tid = threadIdx.x;
    if (tid < NT) cnt[tid] = 0;
    __syncthreads();
    for (int i = tid; i < B; i += blockDim.x)
        atomicAdd(&cnt[task_id[i]], 1);
    __syncthreads();
    if (tid == 0) {
        int s = 0, nw = 0;
        for (int t = 0; t < NT; t++) {
            off[t] = s;
            for (int m = s; m < s + cnt[t]; m += MTILE) {
                g_work_t[nw] = t; g_work_m0[nw] = m; nw++;
            }
            s += cnt[t];
        }
        off[NT] = s;
        g_nwork = nw;
    }
    __syncthreads();
    if (tid <= NT) g_offsets[tid] = off[tid];
    if (tid < NT)  cur[tid] = off[tid];
    __syncthreads();
    for (int i = tid; i < B; i += blockDim.x) {
        int t = task_id[i];
        int p = atomicAdd(&cur[t], 1);
        g_sorted[p]  = i;
        g_rowtask[p] = t;
    }
}

// ---------------- phase B: down-proj split-K, reg-staged f32 A ---------------
// A: LDG x f32 (gather) two iters ahead -> cvt -> STS bf16 into 3-slot ring.
// B: cp.async f32 3-stage + self-mapped convert (R8-proven arithmetic:
//    commits = j+3 after in-loop commit, wait1 => groups <= j+1 complete).
__global__ void __launch_bounds__(256, 2) down_kernel(const float* __restrict__ x,
                                                      const float* __restrict__ Wd) {
    if ((int)blockIdx.y >= g_nwork) return;
    const int t    = g_work_t[blockIdx.y];
    const int m0   = g_work_m0[blockIdx.y];
    const int rows = min(MTILE, g_offsets[t + 1] - m0);
    const int nb   = blockIdx.x & 1;
    const int kc   = blockIdx.x >> 1;
    const int n0   = nb * 128;
    const int ks0  = kc * KCHUNK;

    extern __shared__ __align__(16) char smem[];
    __shared__ int s_idx[MTILE];

    const int tid = threadIdx.x;
    if (tid < MTILE) s_idx[tid] = (tid < rows) ? g_sorted[m0 + tid] : -1;
    __syncthreads();

    const uint32_t sU = smem_u32(smem);
    const float* wsrc = Wd + (size_t)t * SIZE * NDOWN + n0;

    // A geometry: 4 threads per row, 8 floats each; thread covers rows ar, ar+64
    const int ar = tid >> 2, ac = (tid & 3) * 8;
    int ai  = s_idx[ar];       ai  = ai  < 0 ? 0 : ai;
    int ai2 = s_idx[ar + 64];  ai2 = ai2 < 0 ? 0 : ai2;
    const float* ap  = x + (size_t)ai  * SIZE + ks0 + ac;
    const float* ap2 = x + (size_t)ai2 * SIZE + ks0 + ac;

    float4 ra[4];
    auto ldgA = [&](int j) {
        const float* p  = ap  + j * KTILE;
        const float* p2 = ap2 + j * KTILE;
        ra[0] = *(const float4*)(p);
        ra[1] = *(const float4*)(p + 4);
        ra[2] = *(const float4*)(p2);
        ra[3] = *(const float4*)(p2 + 4);
    };
    auto stsA = [&](int j) {
        char* base = smem + (size_t)(j % 3) * A_STAGE;
        *(uint4*)(base + ((size_t)ar * AST + ac) * 2)        = cvt_f4x2(ra[0], ra[1]);
        *(uint4*)(base + ((size_t)(ar + 64) * AST + ac) * 2) = cvt_f4x2(ra[2], ra[3]);
    };

    auto fillB = [&](int j) {
        const int k0 = ks0 + j * KTILE;
        const uint32_t bS = sU + BF32_OFF + (uint32_t)(j % 3) * BF32_STAGE;
#pragma unroll
        for (int i = 0; i < 4; i++) {
            int f = tid + i * 256;
            int kr = f >> 5, seg = (f & 31) * 4;
            cp_async16(bS + 4u * ((uint32_t)kr * 128 + seg),
                       wsrc + (size_t)(k0 + kr) * NDOWN + seg);
        }
        cp_commit();
    };

    float c[2][8][4] = {};
    const int lane = tid & 31, wid = tid >> 5;
    const int wm = wid >> 1, wn = wid & 1;

    const int NIT = KCHUNK / KTILE;   // 32
    ldgA(0);
    fillB(0); fillB(1);
    stsA(0);
    ldgA(1);
    cp_wait1();
    convert_B(smem, tid, 0, 0);

#pragma unroll 4
    for (int j = 0; j < NIT; ++j) {
        __syncthreads();                  // publish A slot j + B bf16 slot j
        if (j + 2 < NIT) fillB(j + 2);
        else             cp_commit();     // commits = j+3
        if (j + 1 < NIT) stsA(j + 1);     // write A slot (j+1)%3, read slot j%3
        if (j + 2 < NIT) ldgA(j + 2);
        cp_wait1();                       // own B f32 groups <= j+1 complete
        if (j + 1 < NIT) convert_B(smem, tid, (j + 1) % 3, (j + 1) % 3);
        compute_tile(sU + (uint32_t)(j % 3) * A_STAGE,
                     sU + BB16_OFF + (uint32_t)(j % 3) * BB16_STAGE,
                     lane, wm, wn, c);
    }

    const int g = lane >> 2, tg = lane & 3;
    __nv_bfloat16* pbase = &g_part[kc][0][0];
#pragma unroll
    for (int mi = 0; mi < 2; mi++) {
        int r0 = wm * 32 + mi * 16 + g;
        int r1 = r0 + 8;
#pragma unroll
        for (int ni = 0; ni < 8; ni++) {
            int col = wn * 64 + ni * 8 + tg * 2;
            if (r0 < rows)
                *(uint32_t*)(pbase + (size_t)(m0 + r0) * NDOWN + n0 + col) =
                    pack_bf16(c[mi][ni][0], c[mi][ni][1]);
            if (r1 < rows)
                *(uint32_t*)(pbase + (size_t)(m0 + r1) * NDOWN + n0 + col) =
                    pack_bf16(c[mi][ni][2], c[mi][ni][3]);
        }
    }
}

// ---------------- phase B2: reduce bf16 partials + bias + silu ---------------
__global__ void __launch_bounds__(1024) reduce_kernel(const float* __restrict__ bd, int B) {
    int gidx = blockIdx.x * 1024 + threadIdx.x;
    if (gidx >= B * (NDOWN / 8)) return;
    int pos  = gidx >> 5;
    int col8 = (gidx & 31) * 8;
    float s[8] = {};
#pragma unroll
    for (int k = 0; k < KSPLIT; k++) {
        uint4 v = *(const uint4*)(&g_part[k][pos][col8]);
        const uint32_t w[4] = {v.x, v.y, v.z, v.w};
#pragma unroll
        for (int q = 0; q < 4; q++) {
            __nv_bfloat162 p = *(const __nv_bfloat162*)&w[q];
            s[2 * q]     += __bfloat162float(p.x);
            s[2 * q + 1] += __bfloat162float(p.y);
        }
    }
    const float* bp = bd + g_rowtask[pos] * NDOWN + col8;
    uint32_t o[4];
#pragma unroll
    for (int q = 0; q < 4; q++) {
        float a0 = s[2 * q] + bp[2 * q];
        float a1 = s[2 * q + 1] + bp[2 * q + 1];
        a0 = a0 / (1.f + __expf(-a0));
        a1 = a1 / (1.f + __expf(-a1));
        o[q] = pack_bf16(a0, a1);
    }
    *(uint4*)(g_act + (size_t)pos * NDOWN + col8) = make_uint4(o[0], o[1], o[2], o[3]);
}

// ---- phase C: up-proj 128x64, 3 CTAs/SM, depth-2 A ring + reg-staged B ------
__global__ void __launch_bounds__(256, 3) up_kernel(const float* __restrict__ x,
                                                    const float* __restrict__ Wu,
                                                    const float* __restrict__ bu,
                                                    float* __restrict__ out) {
    if ((int)blockIdx.y >= g_nwork) return;
    const int t    = g_work_t[blockIdx.y];
    const int m0   = g_work_m0[blockIdx.y];
    const int rows = min(MTILE, g_offsets[t + 1] - m0);
    const int n0   = blockIdx.x * 64;

    extern __shared__ __align__(16) char smem[];
    __shared__ int s_orig[MTILE];

    const int tid = threadIdx.x;
    if (tid < MTILE) s_orig[tid] = (tid < rows) ? g_sorted[m0 + tid] : 0;

    const uint32_t sU = smem_u32(smem);
    const __nv_bfloat16* asrc = g_act + (size_t)m0 * NDOWN;
    const float*         wsrc = Wu + (size_t)t * NDOWN * SIZE + n0;

    auto fillA = [&](int j) {
        const int k0 = j * KTILE;
        const uint32_t aS = sU + (uint32_t)(j % U_ASTAGES) * A_STAGE;
#pragma unroll
        for (int i = 0; i < 2; i++) {
            int f = tid + i * 256;
            int r = f >> 2, seg = (f & 3) * 8;
            cp_async16(aS + 2u * ((uint32_t)r * AST + seg),
                       asrc + (size_t)r * NDOWN + k0 + seg);
        }
        cp_commit();
    };

    const int bkr = tid >> 3, bns = (tid & 7) * 8;
    float4 rb0, rb1;
    auto ldgB = [&](int j) {
        const float* p = wsrc + (size_t)(j * KTILE + bkr) * SIZE + bns;
        rb0 = *(const float4*)(p);
        rb1 = *(const float4*)(p + 4);
    };
    auto stsB = [&](int j) {
        char* d = smem + U_B_OFF + (size_t)(j & 1) * UB16_STAGE
                  + ((size_t)bkr * BST2 + bns) * 2;
        *(uint4*)d = cvt_f4x2(rb0, rb1);
    };

    float c[2][4][4] = {};
    const int lane = tid & 31, wid = tid >> 5;
    const int wm = wid >> 1, wn = wid & 1;

    const int NIT = NDOWN / KTILE;   // 8
    ldgB(0);
    fillA(0); fillA(1); fillA(2);
    stsB(0);
    ldgB(1);
    cp_wait2();

#pragma unroll
    for (int j = 0; j < NIT; ++j) {
        __syncthreads();
        if (j + 3 < NIT) fillA(j + 3);
        else             cp_commit();
        if (j + 1 < NIT) stsB(j + 1);
        if (j + 2 < NIT) ldgB(j + 2);
        cp_wait2();
        compute_tile_n32(sU + (uint32_t)(j % U_ASTAGES) * A_STAGE,
                         sU + U_B_OFF + (uint32_t)(j & 1) * UB16_STAGE,
                         lane, wm, wn, c);
    }

    const int g = lane >> 2, tg = lane & 3;
    const float* bup = bu + (size_t)t * SIZE + n0;
#pragma unroll
    for (int mi = 0; mi < 2; mi++) {
        int r0 = wm * 32 + mi * 16 + g;
        int r1 = r0 + 8;
#pragma unroll
        for (int ni = 0; ni < 4; ni++) {
            int col = wn * 32 + ni * 8 + tg * 2;
            float b0 = bup[col], b1 = bup[col + 1];
            if (r0 < rows) {
                size_t o = (size_t)s_orig[r0] * SIZE + n0 + col;
                out[o]     = x[o]     + c[mi][ni][0] + b0;
                out[o + 1] = x[o + 1] + c[mi][ni][1] + b1;
            }
            if (r1 < rows) {
                size_t o = (size_t)s_orig[r1] * SIZE + n0 + col;
                out[o]     = x[o]     + c[mi][ni][2] + b0;
                out[o + 1] = x[o + 1] + c[mi][ni][3] + b1;
            }
        }
    }
}

// ---------------- launch ----------------
extern "C" void kernel_launch(void* const* d_in, const int* in_sizes, int n_in,
                              void* d_out, int out_size) {
    const float* x       = (const float*)d_in[0];
    const int*   task_id = (const int*)d_in[1];
    const float* Wd      = (const float*)d_in[2];
    const float* bd      = (const float*)d_in[3];
    const float* Wu      = (const float*)d_in[4];
    const float* bu      = (const float*)d_in[5];
    float*       out     = (float*)d_out;
    const int B = in_sizes[1];

    prep_kernel<<<1, 1024>>>(task_id, B);

    cudaFuncSetAttribute(down_kernel, cudaFuncAttributeMaxDynamicSharedMemorySize, D_SMEM);
    cudaFuncSetAttribute(up_kernel,   cudaFuncAttributeMaxDynamicSharedMemorySize, U_SMEM);

    const int maxWork = B / MTILE + NT;
    dim3 gD(2 * KSPLIT, maxWork);   // (8, ...)
    down_kernel<<<gD, 256, D_SMEM>>>(x, Wd);

    reduce_kernel<<<(B * (NDOWN / 8) + 1023) / 1024, 1024>>>(bd, B);

    dim3 gU(SIZE / 64, maxWork);
    up_kernel<<<gU, 256, U_SMEM>>>(x, Wu, bu, out);
}

// round 16
// speedup vs baseline: 1.3415x; 1.3415x over previous
#include <cuda_runtime.h>
#include <cuda_bf16.h>
#include <cstdint>

#define SIZE   4096
#define NDOWN  256
#define NT     16
#define MAXB   4096
#define MTILE  128
#define KSPLIT 8
#define KCHUNK (SIZE / KSPLIT)   // 512
#define KTILE  32
#define NWMAX  (MAXB / MTILE + NT)

#define AST 40    // A smem stride (bf16)
#define BST 136   // B smem stride (down, 128-wide)
#define BST2 72   // B smem stride (up, 64-wide)

// ---- down kernel smem layout (R8-proven) ----
#define A_STAGE    (MTILE * AST * 2)             // 10240
#define BF32_OFF   (3 * A_STAGE)                 // 30720
#define BF32_STAGE (KTILE * 128 * 4)             // 16384
#define BB16_OFF   (BF32_OFF + 3 * BF32_STAGE)   // 79872
#define BB16_STAGE (KTILE * BST * 2)             // 8704
#define D_SMEM     (BB16_OFF + 3 * BB16_STAGE)   // 105984

// ---- up kernel smem layout: 4-stage A ring + 2-slot bf16 B ring ----
#define U_ASTAGES  4
#define U_B_OFF    (U_ASTAGES * A_STAGE)         // 40960
#define UB16_STAGE (KTILE * BST2 * 2)            // 4608
#define U_SMEM     (U_B_OFF + 2 * UB16_STAGE)    // 50176 -> 3 CTAs/SM

// ---------------- device scratch ----------------
__device__ int   g_offsets[NT + 1];
__device__ int   g_sorted[MAXB];
__device__ int   g_work_t[NWMAX];
__device__ int   g_work_m0[NWMAX];
__device__ int   g_nwork;
__device__ int   g_cnt[NWMAX];
__device__ __align__(16) __nv_bfloat16 g_part[KSPLIT][MAXB][NDOWN];
__device__ __align__(16) __nv_bfloat16 g_act[(size_t)MAXB * NDOWN];
__device__ __align__(16) __nv_bfloat16 g_xs[(size_t)MAXB * SIZE];

// ---------------- helpers ----------------
__device__ __forceinline__ uint32_t smem_u32(const void* p) {
    return (uint32_t)__cvta_generic_to_shared(p);
}
__device__ __forceinline__ void cp_async16(uint32_t dst, const void* src) {
    asm volatile("cp.async.cg.shared.global [%0], [%1], 16;\n"
                 :: "r"(dst), "l"(src) : "memory");
}
__device__ __forceinline__ void cp_async16p(uint32_t dst, const void* src, bool pred) {
    int sz = pred ? 16 : 0;
    asm volatile("cp.async.cg.shared.global [%0], [%1], 16, %2;\n"
                 :: "r"(dst), "l"(src), "r"(sz) : "memory");
}
__device__ __forceinline__ void cp_commit() {
    asm volatile("cp.async.commit_group;\n" ::: "memory");
}
__device__ __forceinline__ void cp_wait1() {
    asm volatile("cp.async.wait_group 1;\n" ::: "memory");
}
__device__ __forceinline__ void cp_wait2() {
    asm volatile("cp.async.wait_group 2;\n" ::: "memory");
}
__device__ __forceinline__ uint32_t pack_bf16(float lo, float hi) {
    uint32_t r;
    asm("cvt.rn.bf16x2.f32 %0, %1, %2;" : "=r"(r) : "f"(hi), "f"(lo));
    return r;
}
__device__ __forceinline__ uint4 cvt_f4x2(float4 a, float4 b) {
    uint4 u;
    u.x = pack_bf16(a.x, a.y); u.y = pack_bf16(a.z, a.w);
    u.z = pack_bf16(b.x, b.y); u.w = pack_bf16(b.z, b.w);
    return u;
}
__device__ __forceinline__ void ldsm4(uint32_t& r0, uint32_t& r1, uint32_t& r2, uint32_t& r3,
                                      uint32_t addr) {
    asm volatile("ldmatrix.sync.aligned.m8n8.x4.shared.b16 {%0,%1,%2,%3}, [%4];"
                 : "=r"(r0), "=r"(r1), "=r"(r2), "=r"(r3) : "r"(addr));
}
__device__ __forceinline__ void ldsm4t(uint32_t& r0, uint32_t& r1, uint32_t& r2, uint32_t& r3,
                                       uint32_t addr) {
    asm volatile("ldmatrix.sync.aligned.m8n8.x4.trans.shared.b16 {%0,%1,%2,%3}, [%4];"
                 : "=r"(r0), "=r"(r1), "=r"(r2), "=r"(r3) : "r"(addr));
}
__device__ __forceinline__ void mma_bf16(float& c0, float& c1, float& c2, float& c3,
                                         uint32_t a0, uint32_t a1, uint32_t a2, uint32_t a3,
                                         uint32_t b0, uint32_t b1) {
    asm volatile(
        "mma.sync.aligned.m16n8k16.row.col.f32.bf16.bf16.f32 "
        "{%0,%1,%2,%3}, {%4,%5,%6,%7}, {%8,%9}, {%0,%1,%2,%3};\n"
        : "+f"(c0), "+f"(c1), "+f"(c2), "+f"(c3)
        : "r"(a0), "r"(a1), "r"(a2), "r"(a3), "r"(b0), "r"(b1));
}

// down warp-tile: 32(M) x 64(N) x 32(K); 8 warps = 4x2 over 128x128
__device__ __forceinline__ void compute_tile(uint32_t aSlot, uint32_t bSlot,
                                             int lane, int wm, int wn,
                                             float c[2][8][4]) {
#pragma unroll
    for (int ks = 0; ks < 2; ++ks) {
        uint32_t a[2][4];
#pragma unroll
        for (int mi = 0; mi < 2; mi++) {
            uint32_t addr = aSlot + 2u * ((wm * 32 + mi * 16 + (lane & 15)) * AST
                                          + ks * 16 + (lane >> 4) * 8);
            ldsm4(a[mi][0], a[mi][1], a[mi][2], a[mi][3], addr);
        }
        uint32_t b[8][2];
#pragma unroll
        for (int nb = 0; nb < 4; nb++) {
            uint32_t addr = bSlot + 2u * ((ks * 16 + ((lane >> 3) & 1) * 8 + (lane & 7)) * BST
                                          + wn * 64 + nb * 16 + (lane >> 4) * 8);
            ldsm4t(b[2 * nb][0], b[2 * nb][1], b[2 * nb + 1][0], b[2 * nb + 1][1], addr);
        }
#pragma unroll
        for (int mi = 0; mi < 2; mi++)
#pragma unroll
            for (int ni = 0; ni < 8; ni++)
                mma_bf16(c[mi][ni][0], c[mi][ni][1], c[mi][ni][2], c[mi][ni][3],
                         a[mi][0], a[mi][1], a[mi][2], a[mi][3],
                         b[ni][0], b[ni][1]);
    }
}

// up warp-tile: 32(M) x 32(N) x 32(K); 8 warps = 4x2 over 128x64
__device__ __forceinline__ void compute_tile_n32(uint32_t aSlot, uint32_t bSlot,
                                                 int lane, int wm, int wn,
                                                 float c[2][4][4]) {
#pragma unroll
    for (int ks = 0; ks < 2; ++ks) {
        uint32_t a[2][4];
#pragma unroll
        for (int mi = 0; mi < 2; mi++) {
            uint32_t addr = aSlot + 2u * ((wm * 32 + mi * 16 + (lane & 15)) * AST
                                          + ks * 16 + (lane >> 4) * 8);
            ldsm4(a[mi][0], a[mi][1], a[mi][2], a[mi][3], addr);
        }
        uint32_t b[4][2];
#pragma unroll
        for (int nb = 0; nb < 2; nb++) {
            uint32_t addr = bSlot + 2u * ((ks * 16 + ((lane >> 3) & 1) * 8 + (lane & 7)) * BST2
                                          + wn * 32 + nb * 16 + (lane >> 4) * 8);
            ldsm4t(b[2 * nb][0], b[2 * nb][1], b[2 * nb + 1][0], b[2 * nb + 1][1], addr);
        }
#pragma unroll
        for (int mi = 0; mi < 2; mi++)
#pragma unroll
            for (int ni = 0; ni < 4; ni++)
                mma_bf16(c[mi][ni][0], c[mi][ni][1], c[mi][ni][2], c[mi][ni][3],
                         a[mi][0], a[mi][1], a[mi][2], a[mi][3],
                         b[ni][0], b[ni][1]);
    }
}

// B-stage convert for down (self-mapped)
__device__ __forceinline__ void convert_B(char* smem, int tid, int f32slot, int b16slot) {
#pragma unroll
    for (int i = 0; i < 4; i++) {
        int f = tid + i * 256;
        int kr = f >> 5, seg = (f & 31) * 4;
        float4 v = *(const float4*)(smem + BF32_OFF + (size_t)f32slot * BF32_STAGE
                                    + ((size_t)kr * 128 + seg) * 4);
        *(uint2*)(smem + BB16_OFF + (size_t)b16slot * BB16_STAGE
                  + ((size_t)kr * BST + seg) * 2) =
            make_uint2(pack_bf16(v.x, v.y), pack_bf16(v.z, v.w));
    }
}

// ------------- phase A: fused x->bf16 conversion + counting sort -------------
__global__ void __launch_bounds__(256) xconv_prep_kernel(const float* __restrict__ x,
                                                         const int* __restrict__ task_id,
                                                         int B) {
    if ((int)blockIdx.x < B) {
        const size_t base = ((size_t)blockIdx.x * 256 + threadIdx.x) * 16;
        const float4* s = (const float4*)(x + base);
        uint4* d = (uint4*)(g_xs + base);
        float4 v0 = s[0], v1 = s[1], v2 = s[2], v3 = s[3];
        d[0] = cvt_f4x2(v0, v1);
        d[1] = cvt_f4x2(v2, v3);
        return;
    }
    __shared__ int cnt[NT];
    __shared__ int off[NT + 1];
    __shared__ int cur[NT];
    int tid = threadIdx.x;
    if (tid < NT) cnt[tid] = 0;
    // zero split-K arrival counters (graph-safe re-init every call)
    for (int i = tid; i < NWMAX; i += blockDim.x) g_cnt[i] = 0;
    __syncthreads();
    for (int i = tid; i < B; i += blockDim.x)
        atomicAdd(&cnt[task_id[i]], 1);
    __syncthreads();
    if (tid == 0) {
        int s = 0, nw = 0;
        for (int t = 0; t < NT; t++) {
            off[t] = s;
            for (int m = s; m < s + cnt[t]; m += MTILE) {
                g_work_t[nw] = t; g_work_m0[nw] = m; nw++;
            }
            s += cnt[t];
        }
        off[NT] = s;
        g_nwork = nw;
    }
    __syncthreads();
    if (tid <= NT) g_offsets[tid] = off[tid];
    if (tid < NT)  cur[tid] = off[tid];
    __syncthreads();
    for (int i = tid; i < B; i += blockDim.x) {
        int t = task_id[i];
        int p = atomicAdd(&cur[t], 1);
        g_sorted[p] = i;
    }
}

// --- phase B: down-proj split-K (R8-proven) + fused last-CTA reduction -------
__global__ void __launch_bounds__(256, 2) down_kernel(const float* __restrict__ Wd,
                                                      const float* __restrict__ bd) {
    if ((int)blockIdx.y >= g_nwork) return;
    const int t    = g_work_t[blockIdx.y];
    const int m0   = g_work_m0[blockIdx.y];
    const int rows = min(MTILE, g_offsets[t + 1] - m0);
    const int nb   = blockIdx.x & 1;
    const int kc   = blockIdx.x >> 1;
    const int n0   = nb * 128;
    const int ks0  = kc * KCHUNK;

    extern __shared__ __align__(16) char smem[];
    __shared__ int s_idx[MTILE];
    __shared__ int s_last;

    const int tid = threadIdx.x;
    if (tid < MTILE) s_idx[tid] = (tid < rows) ? g_sorted[m0 + tid] : -1;
    __syncthreads();

    const uint32_t sU = smem_u32(smem);
    const float* wsrc = Wd + (size_t)t * SIZE * NDOWN + n0;

    auto fill = [&](int j) {
        const int k0 = ks0 + j * KTILE;
        const uint32_t aS = sU + (uint32_t)(j % 3) * A_STAGE;
#pragma unroll
        for (int i = 0; i < 2; i++) {
            int f = tid + i * 256;
            int r = f >> 2, seg = (f & 3) * 8;
            int idx = s_idx[r];
            cp_async16p(aS + 2u * ((uint32_t)r * AST + seg),
                        g_xs + (size_t)(idx < 0 ? 0 : idx) * SIZE + k0 + seg, idx >= 0);
        }
        const uint32_t bS = sU + BF32_OFF + (uint32_t)(j % 3) * BF32_STAGE;
#pragma unroll
        for (int i = 0; i < 4; i++) {
            int f = tid + i * 256;
            int kr = f >> 5, seg = (f & 31) * 4;
            cp_async16(bS + 4u * ((uint32_t)kr * 128 + seg),
                       wsrc + (size_t)(k0 + kr) * NDOWN + seg);
        }
        cp_commit();
    };

    float c[2][8][4] = {};
    const int lane = tid & 31, wid = tid >> 5;
    const int wm = wid >> 1, wn = wid & 1;

    const int NIT = KCHUNK / KTILE;   // 16
    fill(0); fill(1);
    cp_wait1();
    convert_B(smem, tid, 0, 0);

#pragma unroll
    for (int j = 0; j < NIT; ++j) {
        __syncthreads();
        if (j + 2 < NIT) fill(j + 2);
        else             cp_commit();
        cp_wait1();
        if (j + 1 < NIT) convert_B(smem, tid, (j + 1) % 3, (j + 1) % 3);
        compute_tile(sU + (uint32_t)(j % 3) * A_STAGE,
                     sU + BB16_OFF + (uint32_t)(j % 3) * BB16_STAGE,
                     lane, wm, wn, c);
    }

    const int g = lane >> 2, tg = lane & 3;
    __nv_bfloat16* pbase = &g_part[kc][0][0];
#pragma unroll
    for (int mi = 0; mi < 2; mi++) {
        int r0 = wm * 32 + mi * 16 + g;
        int r1 = r0 + 8;
#pragma unroll
        for (int ni = 0; ni < 8; ni++) {
            int col = wn * 64 + ni * 8 + tg * 2;
            if (r0 < rows)
                *(uint32_t*)(pbase + (size_t)(m0 + r0) * NDOWN + n0 + col) =
                    pack_bf16(c[mi][ni][0], c[mi][ni][1]);
            if (r1 < rows)
                *(uint32_t*)(pbase + (size_t)(m0 + r1) * NDOWN + n0 + col) =
                    pack_bf16(c[mi][ni][2], c[mi][ni][3]);
        }
    }

    // ---- fused split-K reduction: last of 16 CTAs for this m-tile ----
    __threadfence();
    if (tid == 0)
        s_last = (atomicAdd(&g_cnt[blockIdx.y], 1) == 2 * KSPLIT - 1);
    __syncthreads();
    if (!s_last) return;

    // reduce 128x256 tile: 4096 8-col chunks, 16 per thread (L2-hot reads)
    const float* bp = bd + t * NDOWN;
#pragma unroll
    for (int i = 0; i < 16; i++) {
        int chunk = tid + i * 256;
        int row   = chunk >> 5;
        int col8  = (chunk & 31) * 8;
        if (row >= rows) continue;
        int pos = m0 + row;
        float s[8] = {};
#pragma unroll
        for (int k = 0; k < KSPLIT; k++) {
            uint4 v = *(const uint4*)(&g_part[k][pos][col8]);
            const uint32_t w[4] = {v.x, v.y, v.z, v.w};
#pragma unroll
            for (int q = 0; q < 4; q++) {
                __nv_bfloat162 p = *(const __nv_bfloat162*)&w[q];
                s[2 * q]     += __bfloat162float(p.x);
                s[2 * q + 1] += __bfloat162float(p.y);
            }
        }
        uint32_t o[4];
#pragma unroll
        for (int q = 0; q < 4; q++) {
            float a0 = s[2 * q] + bp[col8 + 2 * q];
            float a1 = s[2 * q + 1] + bp[col8 + 2 * q + 1];
            a0 = a0 / (1.f + __expf(-a0));
            a1 = a1 / (1.f + __expf(-a1));
            o[q] = pack_bf16(a0, a1);
        }
        *(uint4*)(g_act + (size_t)pos * NDOWN + col8) = make_uint4(o[0], o[1], o[2], o[3]);
    }
}

// ---- phase C: up-proj 128x64, 3 CTAs/SM, depth-2 A ring + reg-staged B ------
__global__ void __launch_bounds__(256, 3) up_kernel(const float* __restrict__ x,
                                                    const float* __restrict__ Wu,
                                                    const float* __restrict__ bu,
                                                    float* __restrict__ out) {
    if ((int)blockIdx.y >= g_nwork) return;
    const int t    = g_work_t[blockIdx.y];
    const int m0   = g_work_m0[blockIdx.y];
    const int rows = min(MTILE, g_offsets[t + 1] - m0);
    const int n0   = blockIdx.x * 64;

    extern __shared__ __align__(16) char smem[];
    __shared__ int s_orig[MTILE];

    const int tid = threadIdx.x;
    if (tid < MTILE) s_orig[tid] = (tid < rows) ? g_sorted[m0 + tid] : 0;

    const uint32_t sU = smem_u32(smem);
    const __nv_bfloat16* asrc = g_act + (size_t)m0 * NDOWN;
    const float*         wsrc = Wu + (size_t)t * NDOWN * SIZE + n0;

    auto fillA = [&](int j) {
        const int k0 = j * KTILE;
        const uint32_t aS = sU + (uint32_t)(j % U_ASTAGES) * A_STAGE;
#pragma unroll
        for (int i = 0; i < 2; i++) {
            int f = tid + i * 256;
            int r = f >> 2, seg = (f & 3) * 8;
            cp_async16(aS + 2u * ((uint32_t)r * AST + seg),
                       asrc + (size_t)r * NDOWN + k0 + seg);
        }
        cp_commit();
    };

    const int bkr = tid >> 3, bns = (tid & 7) * 8;
    float4 rb0, rb1;
    auto ldgB = [&](int j) {
        const float* p = wsrc + (size_t)(j * KTILE + bkr) * SIZE + bns;
        rb0 = *(const float4*)(p);
        rb1 = *(const float4*)(p + 4);
    };
    auto stsB = [&](int j) {
        char* d = smem + U_B_OFF + (size_t)(j & 1) * UB16_STAGE
                  + ((size_t)bkr * BST2 + bns) * 2;
        *(uint4*)d = cvt_f4x2(rb0, rb1);
    };

    float c[2][4][4] = {};
    const int lane = tid & 31, wid = tid >> 5;
    const int wm = wid >> 1, wn = wid & 1;

    const int NIT = NDOWN / KTILE;   // 8
    ldgB(0);
    fillA(0); fillA(1); fillA(2);
    stsB(0);
    ldgB(1);
    cp_wait2();

#pragma unroll
    for (int j = 0; j < NIT; ++j) {
        __syncthreads();
        if (j + 3 < NIT) fillA(j + 3);
        else             cp_commit();
        if (j + 1 < NIT) stsB(j + 1);
        if (j + 2 < NIT) ldgB(j + 2);
        cp_wait2();
        compute_tile_n32(sU + (uint32_t)(j % U_ASTAGES) * A_STAGE,
                         sU + U_B_OFF + (uint32_t)(j & 1) * UB16_STAGE,
                         lane, wm, wn, c);
    }

    const int g = lane >> 2, tg = lane & 3;
    const float* bup = bu + (size_t)t * SIZE + n0;
#pragma unroll
    for (int mi = 0; mi < 2; mi++) {
        int r0 = wm * 32 + mi * 16 + g;
        int r1 = r0 + 8;
#pragma unroll
        for (int ni = 0; ni < 4; ni++) {
            int col = wn * 32 + ni * 8 + tg * 2;
            float b0 = bup[col], b1 = bup[col + 1];
            if (r0 < rows) {
                size_t o = (size_t)s_orig[r0] * SIZE + n0 + col;
                out[o]     = x[o]     + c[mi][ni][0] + b0;
                out[o + 1] = x[o + 1] + c[mi][ni][1] + b1;
            }
            if (r1 < rows) {
                size_t o = (size_t)s_orig[r1] * SIZE + n0 + col;
                out[o]     = x[o]     + c[mi][ni][2] + b0;
                out[o + 1] = x[o + 1] + c[mi][ni][3] + b1;
            }
        }
    }
}

// ---------------- launch ----------------
extern "C" void kernel_launch(void* const* d_in, const int* in_sizes, int n_in,
                              void* d_out, int out_size) {
    const float* x       = (const float*)d_in[0];
    const int*   task_id = (const int*)d_in[1];
    const float* Wd      = (const float*)d_in[2];
    const float* bd      = (const float*)d_in[3];
    const float* Wu      = (const float*)d_in[4];
    const float* bu      = (const float*)d_in[5];
    float*       out     = (float*)d_out;
    const int B = in_sizes[1];

    xconv_prep_kernel<<<B + 1, 256>>>(x, task_id, B);

    cudaFuncSetAttribute(down_kernel, cudaFuncAttributeMaxDynamicSharedMemorySize, D_SMEM);
    cudaFuncSetAttribute(up_kernel,   cudaFuncAttributeMaxDynamicSharedMemorySize, U_SMEM);

    const int maxWork = B / MTILE + NT;
    dim3 gD(2 * KSPLIT, maxWork);
    down_kernel<<<gD, 256, D_SMEM>>>(Wd, bd);

    dim3 gU(SIZE / 64, maxWork);
    up_kernel<<<gU, 256, U_SMEM>>>(x, Wu, bu, out);
}

// round 17
// speedup vs baseline: 1.4563x; 1.0856x over previous
#include <cuda_runtime.h>
#include <cuda_bf16.h>
#include <cstdint>

#define SIZE   4096
#define NDOWN  256
#define NT     16
#define MAXB   4096
#define MTILE  128
#define KSPLIT 8
#define KCHUNK (SIZE / KSPLIT)   // 512
#define NWMAX  (MAXB / MTILE + NT)

// ---- down kernel (KTILE=16, dual f32 staging) ----
#define DKT    16
#define AST16  24     // A bf16 stride (K=16 + 8 pad): 48B rows, ldsm conflict-free
#define BST    136    // B bf16 stride (128-wide + 8): 272B rows
#define AF32_STAGE (MTILE * DKT * 4)             // 8192
#define BF32_STAGE (DKT * 128 * 4)               // 8192
#define AB16_STAGE (MTILE * AST16 * 2)           // 6144
#define BB16_STAGE (DKT * BST * 2)               // 4352
#define AF32_OFF   0
#define BF32_OFF   (3 * AF32_STAGE)              // 24576
#define AB16_OFF   (BF32_OFF + 3 * BF32_STAGE)   // 49152
#define BB16_OFF   (AB16_OFF + 3 * AB16_STAGE)   // 67584
#define D_SMEM     (BB16_OFF + 3 * BB16_STAGE)   // 80640 -> 2 CTAs/SM

// ---- up kernel (R14-proven): 4-stage A ring + 2-slot bf16 B ring ----
#define UKT    32
#define ASTU   40     // up A bf16 stride (K=32 + 8)
#define BST2   72     // up B bf16 stride (64-wide + 8)
#define UA_STAGE   (MTILE * ASTU * 2)            // 10240
#define U_ASTAGES  4
#define U_B_OFF    (U_ASTAGES * UA_STAGE)        // 40960
#define UB16_STAGE (UKT * BST2 * 2)              // 4608
#define U_SMEM     (U_B_OFF + 2 * UB16_STAGE)    // 50176 -> 3 CTAs/SM

// ---------------- device scratch ----------------
__device__ int   g_offsets[NT + 1];
__device__ int   g_sorted[MAXB];
__device__ int   g_rowtask[MAXB];
__device__ int   g_work_t[NWMAX];
__device__ int   g_work_m0[NWMAX];
__device__ int   g_nwork;
__device__ __align__(16) __nv_bfloat16 g_part[KSPLIT][MAXB][NDOWN];
__device__ __align__(16) __nv_bfloat16 g_act[(size_t)MAXB * NDOWN];

// ---------------- helpers ----------------
__device__ __forceinline__ uint32_t smem_u32(const void* p) {
    return (uint32_t)__cvta_generic_to_shared(p);
}
__device__ __forceinline__ void cp_async16(uint32_t dst, const void* src) {
    asm volatile("cp.async.cg.shared.global [%0], [%1], 16;\n"
                 :: "r"(dst), "l"(src) : "memory");
}
__device__ __forceinline__ void cp_async16p(uint32_t dst, const void* src, bool pred) {
    int sz = pred ? 16 : 0;
    asm volatile("cp.async.cg.shared.global [%0], [%1], 16, %2;\n"
                 :: "r"(dst), "l"(src), "r"(sz) : "memory");
}
__device__ __forceinline__ void cp_commit() {
    asm volatile("cp.async.commit_group;\n" ::: "memory");
}
__device__ __forceinline__ void cp_wait1() {
    asm volatile("cp.async.wait_group 1;\n" ::: "memory");
}
__device__ __forceinline__ void cp_wait2() {
    asm volatile("cp.async.wait_group 2;\n" ::: "memory");
}
__device__ __forceinline__ uint32_t pack_bf16(float lo, float hi) {
    uint32_t r;
    asm("cvt.rn.bf16x2.f32 %0, %1, %2;" : "=r"(r) : "f"(hi), "f"(lo));
    return r;
}
__device__ __forceinline__ uint4 cvt_f4x2(float4 a, float4 b) {
    uint4 u;
    u.x = pack_bf16(a.x, a.y); u.y = pack_bf16(a.z, a.w);
    u.z = pack_bf16(b.x, b.y); u.w = pack_bf16(b.z, b.w);
    return u;
}
__device__ __forceinline__ void ldsm4(uint32_t& r0, uint32_t& r1, uint32_t& r2, uint32_t& r3,
                                      uint32_t addr) {
    asm volatile("ldmatrix.sync.aligned.m8n8.x4.shared.b16 {%0,%1,%2,%3}, [%4];"
                 : "=r"(r0), "=r"(r1), "=r"(r2), "=r"(r3) : "r"(addr));
}
__device__ __forceinline__ void ldsm4t(uint32_t& r0, uint32_t& r1, uint32_t& r2, uint32_t& r3,
                                       uint32_t addr) {
    asm volatile("ldmatrix.sync.aligned.m8n8.x4.trans.shared.b16 {%0,%1,%2,%3}, [%4];"
                 : "=r"(r0), "=r"(r1), "=r"(r2), "=r"(r3) : "r"(addr));
}
__device__ __forceinline__ void mma_bf16(float& c0, float& c1, float& c2, float& c3,
                                         uint32_t a0, uint32_t a1, uint32_t a2, uint32_t a3,
                                         uint32_t b0, uint32_t b1) {
    asm volatile(
        "mma.sync.aligned.m16n8k16.row.col.f32.bf16.bf16.f32 "
        "{%0,%1,%2,%3}, {%4,%5,%6,%7}, {%8,%9}, {%0,%1,%2,%3};\n"
        : "+f"(c0), "+f"(c1), "+f"(c2), "+f"(c3)
        : "r"(a0), "r"(a1), "r"(a2), "r"(a3), "r"(b0), "r"(b1));
}

// down warp-tile (K=16): 32(M) x 64(N) x 16(K); 8 warps = 4x2 over 128x128
__device__ __forceinline__ void compute_tile16(uint32_t aSlot, uint32_t bSlot,
                                               int lane, int wm, int wn,
                                               float c[2][8][4]) {
    uint32_t a[2][4];
#pragma unroll
    for (int mi = 0; mi < 2; mi++) {
        uint32_t addr = aSlot + 2u * ((wm * 32 + mi * 16 + (lane & 15)) * AST16
                                      + (lane >> 4) * 8);
        ldsm4(a[mi][0], a[mi][1], a[mi][2], a[mi][3], addr);
    }
    uint32_t b[8][2];
#pragma unroll
    for (int nb = 0; nb < 4; nb++) {
        uint32_t addr = bSlot + 2u * ((((lane >> 3) & 1) * 8 + (lane & 7)) * BST
                                      + wn * 64 + nb * 16 + (lane >> 4) * 8);
        ldsm4t(b[2 * nb][0], b[2 * nb][1], b[2 * nb + 1][0], b[2 * nb + 1][1], addr);
    }
#pragma unroll
    for (int mi = 0; mi < 2; mi++)
#pragma unroll
        for (int ni = 0; ni < 8; ni++)
            mma_bf16(c[mi][ni][0], c[mi][ni][1], c[mi][ni][2], c[mi][ni][3],
                     a[mi][0], a[mi][1], a[mi][2], a[mi][3],
                     b[ni][0], b[ni][1]);
}

// up warp-tile: 32(M) x 32(N) x 32(K); 8 warps = 4x2 over 128x64
__device__ __forceinline__ void compute_tile_n32(uint32_t aSlot, uint32_t bSlot,
                                                 int lane, int wm, int wn,
                                                 float c[2][4][4]) {
#pragma unroll
    for (int ks = 0; ks < 2; ++ks) {
        uint32_t a[2][4];
#pragma unroll
        for (int mi = 0; mi < 2; mi++) {
            uint32_t addr = aSlot + 2u * ((wm * 32 + mi * 16 + (lane & 15)) * ASTU
                                          + ks * 16 + (lane >> 4) * 8);
            ldsm4(a[mi][0], a[mi][1], a[mi][2], a[mi][3], addr);
        }
        uint32_t b[4][2];
#pragma unroll
        for (int nb = 0; nb < 2; nb++) {
            uint32_t addr = bSlot + 2u * ((ks * 16 + ((lane >> 3) & 1) * 8 + (lane & 7)) * BST2
                                          + wn * 32 + nb * 16 + (lane >> 4) * 8);
            ldsm4t(b[2 * nb][0], b[2 * nb][1], b[2 * nb + 1][0], b[2 * nb + 1][1], addr);
        }
#pragma unroll
        for (int mi = 0; mi < 2; mi++)
#pragma unroll
            for (int ni = 0; ni < 4; ni++)
                mma_bf16(c[mi][ni][0], c[mi][ni][1], c[mi][ni][2], c[mi][ni][3],
                         a[mi][0], a[mi][1], a[mi][2], a[mi][3],
                         b[ni][0], b[ni][1]);
    }
}

// down converts (self-mapped: each thread converts exactly what it cp.async'd)
__device__ __forceinline__ void convert_A16(char* smem, int tid, int slot) {
#pragma unroll
    for (int i = 0; i < 2; i++) {
        int f = tid + i * 256;
        int r = (f >> 2) & 127, s4 = (f & 3) * 4;
        float4 v = *(const float4*)(smem + AF32_OFF + (size_t)slot * AF32_STAGE
                                    + ((size_t)r * DKT + s4) * 4);
        *(uint2*)(smem + AB16_OFF + (size_t)slot * AB16_STAGE
                  + ((size_t)r * AST16 + s4) * 2) =
            make_uint2(pack_bf16(v.x, v.y), pack_bf16(v.z, v.w));
    }
}
__device__ __forceinline__ void convert_B16(char* smem, int tid, int slot) {
#pragma unroll
    for (int i = 0; i < 2; i++) {
        int f = tid + i * 256;
        int kr = f >> 5, seg = (f & 31) * 4;
        float4 v = *(const float4*)(smem + BF32_OFF + (size_t)slot * BF32_STAGE
                                    + ((size_t)kr * 128 + seg) * 4);
        *(uint2*)(smem + BB16_OFF + (size_t)slot * BB16_STAGE
                  + ((size_t)kr * BST + seg) * 2) =
            make_uint2(pack_bf16(v.x, v.y), pack_bf16(v.z, v.w));
    }
}

// ---------------- phase A: counting sort + worklist ----------------
__global__ void prep_kernel(const int* __restrict__ task_id, int B) {
    __shared__ int cnt[NT];
    __shared__ int off[NT + 1];
    __shared__ int cur[NT];
    int tid = threadIdx.x;
    if (tid < NT) cnt[tid] = 0;
    __syncthreads();
    for (int i = tid; i < B; i += blockDim.x)
        atomicAdd(&cnt[task_id[i]], 1);
    __syncthreads();
    if (tid == 0) {
        int s = 0, nw = 0;
        for (int t = 0; t < NT; t++) {
            off[t] = s;
            for (int m = s; m < s + cnt[t]; m += MTILE) {
                g_work_t[nw] = t; g_work_m0[nw] = m; nw++;
            }
            s += cnt[t];
        }
        off[NT] = s;
        g_nwork = nw;
    }
    __syncthreads();
    if (tid <= NT) g_offsets[tid] = off[tid];
    if (tid < NT)  cur[tid] = off[tid];
    __syncthreads();
    for (int i = tid; i < B; i += blockDim.x) {
        int t = task_id[i];
        int p = atomicAdd(&cur[t], 1);
        g_sorted[p]  = i;
        g_rowtask[p] = t;
    }
}

// --- phase B: down-proj split-K, x f32 consumed directly (KTILE=16) ---------
// R8 pipeline discipline: 3-stage rings, fill(j+2)+commit, wait1, convert(j+1),
// compute(j). A and B both cp.async f32 in ONE group per j.
__global__ void __launch_bounds__(256, 2) down_kernel(const float* __restrict__ x,
                                                      const float* __restrict__ Wd) {
    if ((int)blockIdx.y >= g_nwork) return;
    const int t    = g_work_t[blockIdx.y];
    const int m0   = g_work_m0[blockIdx.y];
    const int rows = min(MTILE, g_offsets[t + 1] - m0);
    const int nb   = blockIdx.x & 1;
    const int kc   = blockIdx.x >> 1;
    const int n0   = nb * 128;
    const int ks0  = kc * KCHUNK;

    extern __shared__ __align__(16) char smem[];
    __shared__ int s_idx[MTILE];

    const int tid = threadIdx.x;
    if (tid < MTILE) s_idx[tid] = (tid < rows) ? g_sorted[m0 + tid] : -1;
    __syncthreads();

    const uint32_t sU = smem_u32(smem);
    const float* wsrc = Wd + (size_t)t * SIZE * NDOWN + n0;

    // A gather geometry: thread serves rows r and r+64, one float4 each
    const int ar = tid >> 2, as4 = (tid & 3) * 4;
    const int ai  = s_idx[ar];
    const int ai2 = s_idx[ar + 64];
    const float* ap  = x + (size_t)(ai  < 0 ? 0 : ai)  * SIZE + ks0 + as4;
    const float* ap2 = x + (size_t)(ai2 < 0 ? 0 : ai2) * SIZE + ks0 + as4;

    auto fill = [&](int j) {
        const int slot = j % 3;
        const uint32_t aS = sU + AF32_OFF + (uint32_t)slot * AF32_STAGE;
        cp_async16p(aS + 4u * ((uint32_t)ar * DKT + as4),          ap  + j * DKT, ai  >= 0);
        cp_async16p(aS + 4u * ((uint32_t)(ar + 64) * DKT + as4),   ap2 + j * DKT, ai2 >= 0);
        const int k0 = ks0 + j * DKT;
        const uint32_t bS = sU + BF32_OFF + (uint32_t)slot * BF32_STAGE;
#pragma unroll
        for (int i = 0; i < 2; i++) {
            int f = tid + i * 256;
            int kr = f >> 5, seg = (f & 31) * 4;
            cp_async16(bS + 4u * ((uint32_t)kr * 128 + seg),
                       wsrc + (size_t)(k0 + kr) * NDOWN + seg);
        }
        cp_commit();
    };

    float c[2][8][4] = {};
    const int lane = tid & 31, wid = tid >> 5;
    const int wm = wid >> 1, wn = wid & 1;

    const int NIT = KCHUNK / DKT;   // 32
    fill(0); fill(1);
    cp_wait1();
    convert_A16(smem, tid, 0);
    convert_B16(smem, tid, 0);

    for (int j = 0; j < NIT; ++j) {
        __syncthreads();
        if (j + 2 < NIT) fill(j + 2);
        else             cp_commit();
        cp_wait1();
        if (j + 1 < NIT) {
            convert_A16(smem, tid, (j + 1) % 3);
            convert_B16(smem, tid, (j + 1) % 3);
        }
        compute_tile16(sU + AB16_OFF + (uint32_t)(j % 3) * AB16_STAGE,
                       sU + BB16_OFF + (uint32_t)(j % 3) * BB16_STAGE,
                       lane, wm, wn, c);
    }

    const int g = lane >> 2, tg = lane & 3;
    __nv_bfloat16* pbase = &g_part[kc][0][0];
#pragma unroll
    for (int mi = 0; mi < 2; mi++) {
        int r0 = wm * 32 + mi * 16 + g;
        int r1 = r0 + 8;
#pragma unroll
        for (int ni = 0; ni < 8; ni++) {
            int col = wn * 64 + ni * 8 + tg * 2;
            if (r0 < rows)
                *(uint32_t*)(pbase + (size_t)(m0 + r0) * NDOWN + n0 + col) =
                    pack_bf16(c[mi][ni][0], c[mi][ni][1]);
            if (r1 < rows)
                *(uint32_t*)(pbase + (size_t)(m0 + r1) * NDOWN + n0 + col) =
                    pack_bf16(c[mi][ni][2], c[mi][ni][3]);
        }
    }
}

// ---------------- phase B2: reduce bf16 partials + bias + silu ---------------
__global__ void __launch_bounds__(1024) reduce_kernel(const float* __restrict__ bd, int B) {
    int gidx = blockIdx.x * 1024 + threadIdx.x;
    if (gidx >= B * (NDOWN / 8)) return;
    int pos  = gidx >> 5;
    int col8 = (gidx & 31) * 8;
    float s[8] = {};
#pragma unroll
    for (int k = 0; k < KSPLIT; k++) {
        uint4 v = *(const uint4*)(&g_part[k][pos][col8]);
        const uint32_t w[4] = {v.x, v.y, v.z, v.w};
#pragma unroll
        for (int q = 0; q < 4; q++) {
            __nv_bfloat162 p = *(const __nv_bfloat162*)&w[q];
            s[2 * q]     += __bfloat162float(p.x);
            s[2 * q + 1] += __bfloat162float(p.y);
        }
    }
    const float* bp = bd + g_rowtask[pos] * NDOWN + col8;
    uint32_t o[4];
#pragma unroll
    for (int q = 0; q < 4; q++) {
        float a0 = s[2 * q] + bp[2 * q];
        float a1 = s[2 * q + 1] + bp[2 * q + 1];
        a0 = a0 / (1.f + __expf(-a0));
        a1 = a1 / (1.f + __expf(-a1));
        o[q] = pack_bf16(a0, a1);
    }
    *(uint4*)(g_act + (size_t)pos * NDOWN + col8) = make_uint4(o[0], o[1], o[2], o[3]);
}

// ---- phase C: up-proj 128x64, 3 CTAs/SM (exact R14-proven) ------------------
__global__ void __launch_bounds__(256, 3) up_kernel(const float* __restrict__ x,
                                                    const float* __restrict__ Wu,
                                                    const float* __restrict__ bu,
                                                    float* __restrict__ out) {
    if ((int)blockIdx.y >= g_nwork) return;
    const int t    = g_work_t[blockIdx.y];
    const int m0   = g_work_m0[blockIdx.y];
    const int rows = min(MTILE, g_offsets[t + 1] - m0);
    const int n0   = blockIdx.x * 64;

    extern __shared__ __align__(16) char smem[];
    __shared__ int s_orig[MTILE];

    const int tid = threadIdx.x;
    if (tid < MTILE) s_orig[tid] = (tid < rows) ? g_sorted[m0 + tid] : 0;

    const uint32_t sU = smem_u32(smem);
    const __nv_bfloat16* asrc = g_act + (size_t)m0 * NDOWN;
    const float*         wsrc = Wu + (size_t)t * NDOWN * SIZE + n0;

    auto fillA = [&](int j) {
        const int k0 = j * UKT;
        const uint32_t aS = sU + (uint32_t)(j % U_ASTAGES) * UA_STAGE;
#pragma unroll
        for (int i = 0; i < 2; i++) {
            int f = tid + i * 256;
            int r = f >> 2, seg = (f & 3) * 8;
            cp_async16(aS + 2u * ((uint32_t)r * ASTU + seg),
                       asrc + (size_t)r * NDOWN + k0 + seg);
        }
        cp_commit();
    };

    const int bkr = tid >> 3, bns = (tid & 7) * 8;
    float4 rb0, rb1;
    auto ldgB = [&](int j) {
        const float* p = wsrc + (size_t)(j * UKT + bkr) * SIZE + bns;
        rb0 = *(const float4*)(p);
        rb1 = *(const float4*)(p + 4);
    };
    auto stsB = [&](int j) {
        char* d = smem + U_B_OFF + (size_t)(j & 1) * UB16_STAGE
                  + ((size_t)bkr * BST2 + bns) * 2;
        *(uint4*)d = cvt_f4x2(rb0, rb1);
    };

    float c[2][4][4] = {};
    const int lane = tid & 31, wid = tid >> 5;
    const int wm = wid >> 1, wn = wid & 1;

    const int NIT = NDOWN / UKT;   // 8
    ldgB(0);
    fillA(0); fillA(1); fillA(2);
    stsB(0);
    ldgB(1);
    cp_wait2();

#pragma unroll
    for (int j = 0; j < NIT; ++j) {
        __syncthreads();
        if (j + 3 < NIT) fillA(j + 3);
        else             cp_commit();
        if (j + 1 < NIT) stsB(j + 1);
        if (j + 2 < NIT) ldgB(j + 2);
        cp_wait2();
        compute_tile_n32(sU + (uint32_t)(j % U_ASTAGES) * UA_STAGE,
                         sU + U_B_OFF + (uint32_t)(j & 1) * UB16_STAGE,
                         lane, wm, wn, c);
    }

    const int g = lane >> 2, tg = lane & 3;
    const float* bup = bu + (size_t)t * SIZE + n0;
#pragma unroll
    for (int mi = 0; mi < 2; mi++) {
        int r0 = wm * 32 + mi * 16 + g;
        int r1 = r0 + 8;
#pragma unroll
        for (int ni = 0; ni < 4; ni++) {
            int col = wn * 32 + ni * 8 + tg * 2;
            float b0 = bup[col], b1 = bup[col + 1];
            if (r0 < rows) {
                size_t o = (size_t)s_orig[r0] * SIZE + n0 + col;
                out[o]     = x[o]     + c[mi][ni][0] + b0;
                out[o + 1] = x[o + 1] + c[mi][ni][1] + b1;
            }
            if (r1 < rows) {
                size_t o = (size_t)s_orig[r1] * SIZE + n0 + col;
                out[o]     = x[o]     + c[mi][ni][2] + b0;
                out[o + 1] = x[o + 1] + c[mi][ni][3] + b1;
            }
        }
    }
}

// ---------------- launch ----------------
extern "C" void kernel_launch(void* const* d_in, const int* in_sizes, int n_in,
                              void* d_out, int out_size) {
    const float* x       = (const float*)d_in[0];
    const int*   task_id = (const int*)d_in[1];
    const float* Wd      = (const float*)d_in[2];
    const float* bd      = (const float*)d_in[3];
    const float* Wu      = (const float*)d_in[4];
    const float* bu      = (const float*)d_in[5];
    float*       out     = (float*)d_out;
    const int B = in_sizes[1];

    prep_kernel<<<1, 1024>>>(task_id, B);

    cudaFuncSetAttribute(down_kernel, cudaFuncAttributeMaxDynamicSharedMemorySize, D_SMEM);
    cudaFuncSetAttribute(up_kernel,   cudaFuncAttributeMaxDynamicSharedMemorySize, U_SMEM);

    const int maxWork = B / MTILE + NT;
    dim3 gD(2 * KSPLIT, maxWork);
    down_kernel<<<gD, 256, D_SMEM>>>(x, Wd);

    reduce_kernel<<<(B * (NDOWN / 8) + 1023) / 1024, 1024>>>(bd, B);

    dim3 gU(SIZE / 64, maxWork);
    up_kernel<<<gU, 256, U_SMEM>>>(x, Wu, bu, out);
}